// round 8
// baseline (speedup 1.0000x reference)
#include <cuda_runtime.h>
#include <cstdint>

#define NLINKS   10000
#define NPATHS   100000
#define PLEN     8
#define HDIM     32
#define RDIM     8
#define TROUNDS  8
#define EDGES    (NPATHS * PLEN)

typedef unsigned long long ULL;

// ---------------- scratch (no cudaMalloc allowed) ----------------
__device__ __align__(16) float g_link_state[NLINKS * HDIM];
__device__ __align__(16) float g_path_state[NPATHS * HDIM];
__device__ __align__(16) float g_hs[(size_t)EDGES * HDIM];   // [s][path][32]
__device__ __align__(16) float g_gi[NLINKS * 96];            // per-link gi precompute
__device__ int   g_lk[EDGES];                  // link per slot t = 8p+s
__device__ int   g_srow[EDGES];                // sorted pos -> row (s*NPATHS+p)
__device__ int   g_hist[NLINKS];
__device__ int   g_off[NLINKS + 1];
__device__ int   g_cur[NLINKS];

// ---------------- helpers ----------------
__device__ __forceinline__ ULL fma2(ULL a, ULL b, ULL c) {
    ULL d;
    asm("fma.rn.f32x2 %0, %1, %2, %3;" : "=l"(d) : "l"(a), "l"(b), "l"(c));
    return d;
}
__device__ __forceinline__ ULL mul2(ULL a, ULL b) {
    ULL d;
    asm("mul.rn.f32x2 %0, %1, %2;" : "=l"(d) : "l"(a), "l"(b));
    return d;
}
__device__ __forceinline__ ULL pk(float lo, float hi) {
    ULL r;
    asm("mov.b64 %0, {%1, %2};" : "=l"(r) : "f"(lo), "f"(hi));
    return r;
}
__device__ __forceinline__ float hsum2(ULL v) {
    float lo, hi;
    asm("mov.b64 {%0, %1}, %2;" : "=f"(lo), "=f"(hi) : "l"(v));
    return lo + hi;
}
__device__ __forceinline__ float tanh_fast(float x) {
    float y;
    asm("tanh.approx.f32 %0, %1;" : "=f"(y) : "f"(x));
    return y;
}
__device__ __forceinline__ float sigmoid_fast(float x) {
    return fmaf(0.5f, tanh_fast(0.5f * x), 0.5f);
}

// ---------------- setup A: states, lk map, hist zero -----------------------
__global__ void k_setupA(const float* __restrict__ cap, const float* __restrict__ bw,
                         const int* __restrict__ paths, const int* __restrict__ seqs,
                         const int* __restrict__ links) {
    int i = blockIdx.x * blockDim.x + threadIdx.x;
    if (i < NPATHS * HDIM) g_path_state[i] = ((i & (HDIM - 1)) == 0) ? bw[i / HDIM] : 0.f;
    if (i < NLINKS * HDIM) g_link_state[i] = ((i & (HDIM - 1)) == 0) ? cap[i / HDIM] : 0.f;
    if (i < NLINKS) g_hist[i] = 0;
    if (i < EDGES) g_lk[paths[i] * PLEN + seqs[i]] = links[i];
}

// ---------------- gi matvec from link_state (round-0 only) -----------------
__device__ __forceinline__ void gi_warp(int w, int lane,
                                        const float* sWT, const float* sb) {
    float h = g_link_state[w * HDIM + lane];
    float a0 = sb[lane], a1 = sb[32 + lane], a2 = sb[64 + lane];
#pragma unroll
    for (int k = 0; k < 32; k++) {
        float hv = __shfl_sync(0xffffffffu, h, k);
        a0 += hv * sWT[k * 96 + lane];
        a1 += hv * sWT[k * 96 + 32 + lane];
        a2 += hv * sWT[k * 96 + 64 + lane];
    }
    g_gi[w * 96 + lane] = a0;
    g_gi[w * 96 + 32 + lane] = a1;
    g_gi[w * 96 + 64 + lane] = a2;
}

// ---------------- setup B: histogram + round-0 gi --------------------------
#define HB ((EDGES + 255) / 256)
#define GB ((NLINKS * 32 + 255) / 256)
__global__ __launch_bounds__(256) void k_setupB(
    const int* __restrict__ links,
    const float* __restrict__ pWih, const float* __restrict__ pbih,
    const float* __restrict__ pbhh) {
    if (blockIdx.x < HB) {
        int e = blockIdx.x * 256 + threadIdx.x;
        if (e < EDGES) atomicAdd(&g_hist[links[e]], 1);
        return;
    }
    __shared__ float sWT[HDIM * 96];
    __shared__ float sb[96];
    for (int i = threadIdx.x; i < 96 * HDIM; i += 256) {
        int j = i / HDIM, k = i % HDIM;
        sWT[k * 96 + j] = pWih[i];
    }
    for (int i = threadIdx.x; i < 96; i += 256)
        sb[i] = pbih[i] + (i < 64 ? pbhh[i] : 0.f);
    __syncthreads();
    int w = ((blockIdx.x - HB) * 256 + threadIdx.x) >> 5;
    int lane = threadIdx.x & 31;
    if (w < NLINKS) gi_warp(w, lane, sWT, sb);
}

// ---------------- scan (offsets + cursors) ---------------------------------
__global__ void k_scan() {
    __shared__ int part[1024];
    int tid = threadIdx.x;
    const int CH = (NLINKS + 1023) / 1024;
    int base = tid * CH;
    int s = 0;
    for (int i = 0; i < CH; i++) {
        int idx = base + i;
        if (idx < NLINKS) s += g_hist[idx];
    }
    part[tid] = s;
    __syncthreads();
    for (int off = 1; off < 1024; off <<= 1) {
        int add = (tid >= off) ? part[tid - off] : 0;
        __syncthreads();
        part[tid] += add;
        __syncthreads();
    }
    int run = (tid == 0) ? 0 : part[tid - 1];
    for (int i = 0; i < CH; i++) {
        int idx = base + i;
        if (idx < NLINKS) {
            g_off[idx] = run;
            g_cur[idx] = run;
            run += g_hist[idx];
        }
    }
    if (tid == 1023) g_off[NLINKS] = part[1023];
}

// ---------------- path GRU (dominant kernel) ----------------
// ONE warp per CTA, 2 paths per thread (64 paths/CTA). Weight LDS.128
// broadcasts amortized over both paths. IMPORTANT: hA/hB registers hold the
// PREVIOUS-step hidden throughout the j4 loop (all gates must see old h);
// new values go to sH only, registers refreshed after the loop.
__global__ __launch_bounds__(32) void k_path(
    int build, const float* __restrict__ pWhh, const float* __restrict__ pbhh) {
    __shared__ __align__(16) float sW[96 * HDIM];   // 12.3 KB
    __shared__ __align__(16) float sBn[HDIM];
    __shared__ __align__(16) float sGi[64 * 100];   // 25.6 KB
    __shared__ __align__(16) float sH[64 * 36];     // 9.2 KB
    __shared__ int sLk[64];

    int lane = threadIdx.x;
    {
        const float4* src = (const float4*)pWhh;
        float4* dst = (float4*)sW;
#pragma unroll
        for (int i = 0; i < 24; i++) dst[i * 32 + lane] = src[i * 32 + lane];
        sBn[lane] = pbhh[64 + lane];
    }
    __syncwarp();

    int pbase = blockIdx.x * 64;
    int p0 = pbase + lane;
    int p1 = p0 + 32;
    bool v1 = (p1 < NPATHS);
    int p1s = v1 ? p1 : p0;
    unsigned sgi_base = (unsigned)__cvta_generic_to_shared(sGi);

    ULL hA[16], hB[16];
    {
        const ulonglong2* sA = (const ulonglong2*)&g_path_state[p0 * HDIM];
        const ulonglong2* sB = (const ulonglong2*)&g_path_state[p1s * HDIM];
#pragma unroll
        for (int i = 0; i < 8; i++) {
            ulonglong2 a = sA[i], b = sB[i];
            hA[2 * i] = a.x; hA[2 * i + 1] = a.y;
            hB[2 * i] = b.x; hB[2 * i + 1] = b.y;
        }
    }

    int lk0 = g_lk[p0 * PLEN];
    int lk1 = g_lk[p1s * PLEN];

    const float* gi0 = &sGi[lane * 100];
    const float* gi1 = &sGi[(lane + 32) * 100];
    float* myH0 = &sH[lane * 36];
    float* myH1 = &sH[(lane + 32) * 36];

#pragma unroll 1
    for (int s = 0; s < PLEN; s++) {
        sLk[lane] = lk0;
        sLk[32 + lane] = lk1;
        __syncwarp();
        // stage 64 gi rows (64 x 384B) coalesced: 48 x 16B per lane
#pragma unroll
        for (int it = 0; it < 48; it++) {
            int idx = it * 32 + lane;
            int m = idx / 24;
            int c = idx - m * 24;
            int row = sLk[m];
            const float* srcp = &g_gi[row * 96 + c * 4];
            unsigned dst = sgi_base + (unsigned)(m * 400 + c * 16);
            asm volatile("cp.async.cg.shared.global [%0], [%1], 16;" :: "r"(dst), "l"(srcp));
        }
        asm volatile("cp.async.commit_group;");

        if (build) {
            int pos0 = atomicAdd(&g_cur[lk0], 1);
            g_srow[pos0] = s * NPATHS + p0;
            if (v1) {
                int pos1 = atomicAdd(&g_cur[lk1], 1);
                g_srow[pos1] = s * NPATHS + p1;
            }
        }
        // prefetch next step's links
        if (s + 1 < PLEN) {
            lk0 = g_lk[p0 * PLEN + s + 1];
            lk1 = g_lk[p1s * PLEN + s + 1];
        }
        asm volatile("cp.async.wait_group 0;" ::: "memory");
        __syncwarp();

#pragma unroll 1
        for (int j4 = 0; j4 < 8; j4++) {
            float4 gr0 = *(const float4*)(gi0 + j4 * 4);
            float4 gz0 = *(const float4*)(gi0 + 32 + j4 * 4);
            float4 gn0 = *(const float4*)(gi0 + 64 + j4 * 4);
            float4 gr1 = *(const float4*)(gi1 + j4 * 4);
            float4 gz1 = *(const float4*)(gi1 + 32 + j4 * 4);
            float4 gn1 = *(const float4*)(gi1 + 64 + j4 * 4);
            float4 bn4 = *(const float4*)(sBn + j4 * 4);

            float zzA[4], nnA[4], zzB[4], nnB[4];
#pragma unroll
            for (int u = 0; u < 4; u++) {
                int jj = j4 * 4 + u;
                ULL arA0 = 0, arA1 = 0, azA0 = 0, azA1 = 0, anA0 = 0, anA1 = 0;
                ULL arB0 = 0, arB1 = 0, azB0 = 0, azB1 = 0, anB0 = 0, anB1 = 0;
                const ulonglong2* wr = (const ulonglong2*)&sW[jj * HDIM];
                const ulonglong2* wz = (const ulonglong2*)&sW[(32 + jj) * HDIM];
                const ulonglong2* wn = (const ulonglong2*)&sW[(64 + jj) * HDIM];
#pragma unroll
                for (int q = 0; q < 4; q++) {
                    ulonglong2 w;
                    w = wr[q];
                    arA0 = fma2(hA[2 * q], w.x, arA0);     arA0 = fma2(hA[2 * q + 1], w.y, arA0);
                    arB0 = fma2(hB[2 * q], w.x, arB0);     arB0 = fma2(hB[2 * q + 1], w.y, arB0);
                    w = wr[q + 4];
                    arA1 = fma2(hA[2 * q + 8], w.x, arA1); arA1 = fma2(hA[2 * q + 9], w.y, arA1);
                    arB1 = fma2(hB[2 * q + 8], w.x, arB1); arB1 = fma2(hB[2 * q + 9], w.y, arB1);
                    w = wz[q];
                    azA0 = fma2(hA[2 * q], w.x, azA0);     azA0 = fma2(hA[2 * q + 1], w.y, azA0);
                    azB0 = fma2(hB[2 * q], w.x, azB0);     azB0 = fma2(hB[2 * q + 1], w.y, azB0);
                    w = wz[q + 4];
                    azA1 = fma2(hA[2 * q + 8], w.x, azA1); azA1 = fma2(hA[2 * q + 9], w.y, azA1);
                    azB1 = fma2(hB[2 * q + 8], w.x, azB1); azB1 = fma2(hB[2 * q + 9], w.y, azB1);
                    w = wn[q];
                    anA0 = fma2(hA[2 * q], w.x, anA0);     anA0 = fma2(hA[2 * q + 1], w.y, anA0);
                    anB0 = fma2(hB[2 * q], w.x, anB0);     anB0 = fma2(hB[2 * q + 1], w.y, anB0);
                    w = wn[q + 4];
                    anA1 = fma2(hA[2 * q + 8], w.x, anA1); anA1 = fma2(hA[2 * q + 9], w.y, anA1);
                    anB1 = fma2(hB[2 * q + 8], w.x, anB1); anB1 = fma2(hB[2 * q + 9], w.y, anB1);
                }
                float girA = (u == 0) ? gr0.x : (u == 1) ? gr0.y : (u == 2) ? gr0.z : gr0.w;
                float gizA = (u == 0) ? gz0.x : (u == 1) ? gz0.y : (u == 2) ? gz0.z : gz0.w;
                float ginA = (u == 0) ? gn0.x : (u == 1) ? gn0.y : (u == 2) ? gn0.z : gn0.w;
                float girB = (u == 0) ? gr1.x : (u == 1) ? gr1.y : (u == 2) ? gr1.z : gr1.w;
                float gizB = (u == 0) ? gz1.x : (u == 1) ? gz1.y : (u == 2) ? gz1.z : gz1.w;
                float ginB = (u == 0) ? gn1.x : (u == 1) ? gn1.y : (u == 2) ? gn1.z : gn1.w;
                float bnv = (u == 0) ? bn4.x : (u == 1) ? bn4.y : (u == 2) ? bn4.z : bn4.w;

                float rA = sigmoid_fast(girA + hsum2(arA0) + hsum2(arA1));
                float zA = sigmoid_fast(gizA + hsum2(azA0) + hsum2(azA1));
                float nvA = tanh_fast(ginA + rA * (hsum2(anA0) + hsum2(anA1) + bnv));
                float rB = sigmoid_fast(girB + hsum2(arB0) + hsum2(arB1));
                float zB = sigmoid_fast(gizB + hsum2(azB0) + hsum2(azB1));
                float nvB = tanh_fast(ginB + rB * (hsum2(anB0) + hsum2(anB1) + bnv));
                zzA[u] = zA; nnA[u] = nvA;
                zzB[u] = zB; nnB[u] = nvB;
            }
            // blend in packed form; write ONLY to sH (hA/hB must stay = old h
            // for the remaining j4 iterations' dot products)
            ULL a01 = fma2(pk(zzA[0], zzA[1]), hA[2 * j4],
                           mul2(pk(1.f - zzA[0], 1.f - zzA[1]), pk(nnA[0], nnA[1])));
            ULL a23 = fma2(pk(zzA[2], zzA[3]), hA[2 * j4 + 1],
                           mul2(pk(1.f - zzA[2], 1.f - zzA[3]), pk(nnA[2], nnA[3])));
            ULL b01 = fma2(pk(zzB[0], zzB[1]), hB[2 * j4],
                           mul2(pk(1.f - zzB[0], 1.f - zzB[1]), pk(nnB[0], nnB[1])));
            ULL b23 = fma2(pk(zzB[2], zzB[3]), hB[2 * j4 + 1],
                           mul2(pk(1.f - zzB[2], 1.f - zzB[3]), pk(nnB[2], nnB[3])));
            ulonglong2 va; va.x = a01; va.y = a23;
            ulonglong2 vb; vb.x = b01; vb.y = b23;
            ((ulonglong2*)myH0)[j4] = va;
            ((ulonglong2*)myH1)[j4] = vb;
        }

        // refresh registers with the new hidden (after ALL gates computed)
#pragma unroll
        for (int i = 0; i < 8; i++) {
            ulonglong2 a = ((const ulonglong2*)myH0)[i];
            ulonglong2 b = ((const ulonglong2*)myH1)[i];
            hA[2 * i] = a.x; hA[2 * i + 1] = a.y;
            hB[2 * i] = b.x; hB[2 * i + 1] = b.y;
        }

        __syncwarp();
        // vectorized transpose store: 64 rows x 32 floats = 512 float4
#pragma unroll
        for (int i = 0; i < 16; i++) {
            int fidx = i * 32 + lane;
            int row = fidx >> 3;
            int c = (fidx & 7) * 4;
            float4 v = *(const float4*)&sH[row * 36 + c];
            int pp = pbase + row;
            if (pp < NPATHS)
                *(float4*)&g_hs[((size_t)s * NPATHS + pp) * HDIM + c] = v;
        }
        __syncwarp();
    }

    {
        ulonglong2* dA = (ulonglong2*)&g_path_state[p0 * HDIM];
#pragma unroll
        for (int i = 0; i < 8; i++) {
            ulonglong2 v; v.x = hA[2 * i]; v.y = hA[2 * i + 1];
            dA[i] = v;
        }
        if (v1) {
            ulonglong2* dB = (ulonglong2*)&g_path_state[p1 * HDIM];
#pragma unroll
            for (int i = 0; i < 8; i++) {
                ulonglong2 v; v.x = hB[2 * i]; v.y = hB[2 * i + 1];
                dB[i] = v;
            }
        }
    }
}

// ---------- link aggregation + link GRU + fused next-round gi --------------
__global__ __launch_bounds__(256) void k_link(
    int dogi,
    const float* __restrict__ lWih, const float* __restrict__ lWhh,
    const float* __restrict__ lbih, const float* __restrict__ lbhh,
    const float* __restrict__ pWih, const float* __restrict__ pbih,
    const float* __restrict__ pbhh) {
    __shared__ float sWihT[3 * HDIM * HDIM];  // [k][j]
    __shared__ float sWhhT[3 * HDIM * HDIM];
    __shared__ float sPT[3 * HDIM * HDIM];    // path Wih^T for gi
    __shared__ float sbi[96], sbh[96], sgb[96];

    for (int i = threadIdx.x; i < 3 * HDIM * HDIM; i += 256) {
        int j = i / HDIM, k = i % HDIM;
        sWihT[k * 96 + j] = lWih[i];
        sWhhT[k * 96 + j] = lWhh[i];
        sPT[k * 96 + j] = pWih[i];
    }
    for (int i = threadIdx.x; i < 96; i += 256) {
        sbi[i] = lbih[i];
        sbh[i] = lbhh[i];
        sgb[i] = pbih[i] + (i < 64 ? pbhh[i] : 0.f);
    }
    __syncthreads();

    int w = (blockIdx.x * 256 + threadIdx.x) >> 5;
    int lane = threadIdx.x & 31;
    if (w >= NLINKS) return;

    int b = g_off[w], e = g_off[w + 1];
    float x0 = 0.f, x1 = 0.f, x2s = 0.f, x3 = 0.f;
    int i = b;
    for (; i + 4 <= e; i += 4) {
        int r0 = g_srow[i], r1 = g_srow[i + 1], r2 = g_srow[i + 2], r3 = g_srow[i + 3];
        x0 += g_hs[(size_t)r0 * HDIM + lane];
        x1 += g_hs[(size_t)r1 * HDIM + lane];
        x2s += g_hs[(size_t)r2 * HDIM + lane];
        x3 += g_hs[(size_t)r3 * HDIM + lane];
    }
    for (; i < e; i++) x0 += g_hs[(size_t)g_srow[i] * HDIM + lane];
    float x = (x0 + x1) + (x2s + x3);

    float h = g_link_state[w * HDIM + lane];

    float air = sbi[lane], aiz = sbi[32 + lane], ain = sbi[64 + lane];
    float ahr = sbh[lane], ahz = sbh[32 + lane], ahn = sbh[64 + lane];
#pragma unroll
    for (int k = 0; k < 32; k++) {
        float xv = __shfl_sync(0xffffffffu, x, k);
        float hv = __shfl_sync(0xffffffffu, h, k);
        air += xv * sWihT[k * 96 + lane];
        aiz += xv * sWihT[k * 96 + 32 + lane];
        ain += xv * sWihT[k * 96 + 64 + lane];
        ahr += hv * sWhhT[k * 96 + lane];
        ahz += hv * sWhhT[k * 96 + 32 + lane];
        ahn += hv * sWhhT[k * 96 + 64 + lane];
    }
    float r = sigmoid_fast(air + ahr);
    float z = sigmoid_fast(aiz + ahz);
    float nv = tanh_fast(ain + r * ahn);
    float hnew = (1.f - z) * nv + z * h;
    g_link_state[w * HDIM + lane] = hnew;

    if (dogi) {
        float a0 = sgb[lane], a1 = sgb[32 + lane], a2 = sgb[64 + lane];
#pragma unroll
        for (int k = 0; k < 32; k++) {
            float hv = __shfl_sync(0xffffffffu, hnew, k);
            a0 += hv * sPT[k * 96 + lane];
            a1 += hv * sPT[k * 96 + 32 + lane];
            a2 += hv * sPT[k * 96 + 64 + lane];
        }
        g_gi[w * 96 + lane] = a0;
        g_gi[w * 96 + 32 + lane] = a1;
        g_gi[w * 96 + 64 + lane] = a2;
    }
}

// ---------------- readout MLP ----------------
__global__ __launch_bounds__(256) void k_readout(
    const float* __restrict__ W1, const float* __restrict__ b1,
    const float* __restrict__ W2, const float* __restrict__ b2,
    const float* __restrict__ W3, const float* __restrict__ b3,
    float* __restrict__ out) {
    __shared__ float s1[RDIM * HDIM], sb1[RDIM], s2[RDIM * RDIM], sb2[RDIM], s3[RDIM], sb3;
    for (int i = threadIdx.x; i < RDIM * HDIM; i += 256) s1[i] = W1[i];
    if (threadIdx.x < RDIM * RDIM) s2[threadIdx.x] = W2[threadIdx.x];
    if (threadIdx.x < RDIM) {
        sb1[threadIdx.x] = b1[threadIdx.x];
        sb2[threadIdx.x] = b2[threadIdx.x];
        s3[threadIdx.x] = W3[threadIdx.x];
    }
    if (threadIdx.x == 0) sb3 = b3[0];
    __syncthreads();

    int p = blockIdx.x * 256 + threadIdx.x;
    if (p >= NPATHS) return;

    float x[HDIM];
    {
        const float4* src = (const float4*)&g_path_state[p * HDIM];
#pragma unroll
        for (int i = 0; i < 8; i++) {
            float4 v = src[i];
            x[4 * i] = v.x; x[4 * i + 1] = v.y; x[4 * i + 2] = v.z; x[4 * i + 3] = v.w;
        }
    }
    float y1[RDIM];
#pragma unroll
    for (int i = 0; i < RDIM; i++) {
        float d = sb1[i];
#pragma unroll
        for (int k = 0; k < HDIM; k++) d += x[k] * s1[i * HDIM + k];
        y1[i] = fmaxf(d, 0.f);
    }
    float y2[RDIM];
#pragma unroll
    for (int i = 0; i < RDIM; i++) {
        float d = sb2[i];
#pragma unroll
        for (int k = 0; k < RDIM; k++) d += y1[k] * s2[i * RDIM + k];
        y2[i] = fmaxf(d, 0.f);
    }
    float o = sb3;
#pragma unroll
    for (int k = 0; k < RDIM; k++) o += y2[k] * s3[k];
    out[p] = o;
}

// ---------------- launch ----------------
extern "C" void kernel_launch(void* const* d_in, const int* in_sizes, int n_in,
                              void* d_out, int out_size) {
    const int* links = (const int*)d_in[0];
    const int* paths = (const int*)d_in[1];
    const int* seqs  = (const int*)d_in[2];
    const float* cap = (const float*)d_in[3];
    const float* bw  = (const float*)d_in[4];
    const float* pWih = (const float*)d_in[5];
    const float* pWhh = (const float*)d_in[6];
    const float* pbih = (const float*)d_in[7];
    const float* pbhh = (const float*)d_in[8];
    const float* lWih = (const float*)d_in[9];
    const float* lWhh = (const float*)d_in[10];
    const float* lbih = (const float*)d_in[11];
    const float* lbhh = (const float*)d_in[12];
    const float* W1 = (const float*)d_in[13];
    const float* b1 = (const float*)d_in[14];
    const float* W2 = (const float*)d_in[15];
    const float* b2 = (const float*)d_in[16];
    const float* W3 = (const float*)d_in[17];
    const float* b3 = (const float*)d_in[18];
    float* out = (float*)d_out;

    (void)in_sizes; (void)n_in; (void)out_size;

    k_setupA<<<(NPATHS * HDIM + 255) / 256, 256>>>(cap, bw, paths, seqs, links);
    k_setupB<<<HB + GB, 256>>>(links, pWih, pbih, pbhh);
    k_scan<<<1, 1024>>>();

    for (int r = 0; r < TROUNDS; r++) {
        k_path<<<(NPATHS + 63) / 64, 32>>>(r == 0 ? 1 : 0, pWhh, pbhh);
        k_link<<<(NLINKS + 7) / 8, 256>>>(r + 1 < TROUNDS ? 1 : 0,
                                          lWih, lWhh, lbih, lbhh,
                                          pWih, pbih, pbhh);
    }
    k_readout<<<(NPATHS + 255) / 256, 256>>>(W1, b1, W2, b2, W3, b3, out);
}

// round 10
// speedup vs baseline: 1.2338x; 1.2338x over previous
#include <cuda_runtime.h>
#include <cstdint>

#define NLINKS   10000
#define NPATHS   100000
#define PLEN     8
#define HDIM     32
#define RDIM     8
#define TROUNDS  8
#define EDGES    (NPATHS * PLEN)

typedef unsigned long long ULL;

// ---------------- scratch (no cudaMalloc allowed) ----------------
__device__ __align__(16) float g_link_state[NLINKS * HDIM];
__device__ __align__(16) float g_path_state[NPATHS * HDIM];
__device__ __align__(16) float g_hs[(size_t)EDGES * HDIM];   // [s][path][32]
__device__ __align__(16) float g_gi[NLINKS * 96];            // per-link gi precompute
__device__ int   g_lk[EDGES];                  // link per slot t = 8p+s
__device__ int   g_srow[EDGES];                // sorted pos -> row (s*NPATHS+p)
__device__ int   g_hist[NLINKS];
__device__ int   g_off[NLINKS + 1];
__device__ int   g_cur[NLINKS];

// ---------------- helpers ----------------
__device__ __forceinline__ ULL fma2(ULL a, ULL b, ULL c) {
    ULL d;
    asm("fma.rn.f32x2 %0, %1, %2, %3;" : "=l"(d) : "l"(a), "l"(b), "l"(c));
    return d;
}
__device__ __forceinline__ ULL mul2(ULL a, ULL b) {
    ULL d;
    asm("mul.rn.f32x2 %0, %1, %2;" : "=l"(d) : "l"(a), "l"(b));
    return d;
}
__device__ __forceinline__ ULL pk(float lo, float hi) {
    ULL r;
    asm("mov.b64 %0, {%1, %2};" : "=l"(r) : "f"(lo), "f"(hi));
    return r;
}
__device__ __forceinline__ float hsum2(ULL v) {
    float lo, hi;
    asm("mov.b64 {%0, %1}, %2;" : "=f"(lo), "=f"(hi) : "l"(v));
    return lo + hi;
}
__device__ __forceinline__ float tanh_fast(float x) {
    float y;
    asm("tanh.approx.f32 %0, %1;" : "=f"(y) : "f"(x));
    return y;
}
__device__ __forceinline__ float sigmoid_fast(float x) {
    return fmaf(0.5f, tanh_fast(0.5f * x), 0.5f);
}

// ---------------- setup A: states, lk map, hist zero -----------------------
__global__ void k_setupA(const float* __restrict__ cap, const float* __restrict__ bw,
                         const int* __restrict__ paths, const int* __restrict__ seqs,
                         const int* __restrict__ links) {
    int i = blockIdx.x * blockDim.x + threadIdx.x;
    if (i < NPATHS * HDIM) g_path_state[i] = ((i & (HDIM - 1)) == 0) ? bw[i / HDIM] : 0.f;
    if (i < NLINKS * HDIM) g_link_state[i] = ((i & (HDIM - 1)) == 0) ? cap[i / HDIM] : 0.f;
    if (i < NLINKS) g_hist[i] = 0;
    if (i < EDGES) g_lk[paths[i] * PLEN + seqs[i]] = links[i];
}

// ---------------- gi matvec from link_state (round-0 only) -----------------
__device__ __forceinline__ void gi_warp(int w, int lane,
                                        const float* sWT, const float* sb) {
    float h = g_link_state[w * HDIM + lane];
    float a0 = sb[lane], a1 = sb[32 + lane], a2 = sb[64 + lane];
#pragma unroll
    for (int k = 0; k < 32; k++) {
        float hv = __shfl_sync(0xffffffffu, h, k);
        a0 += hv * sWT[k * 96 + lane];
        a1 += hv * sWT[k * 96 + 32 + lane];
        a2 += hv * sWT[k * 96 + 64 + lane];
    }
    g_gi[w * 96 + lane] = a0;
    g_gi[w * 96 + 32 + lane] = a1;
    g_gi[w * 96 + 64 + lane] = a2;
}

// ---------------- setup B: histogram + round-0 gi --------------------------
#define HB ((EDGES + 255) / 256)
#define GB ((NLINKS * 32 + 255) / 256)
__global__ __launch_bounds__(256) void k_setupB(
    const int* __restrict__ links,
    const float* __restrict__ pWih, const float* __restrict__ pbih,
    const float* __restrict__ pbhh) {
    if (blockIdx.x < HB) {
        int e = blockIdx.x * 256 + threadIdx.x;
        if (e < EDGES) atomicAdd(&g_hist[links[e]], 1);
        return;
    }
    __shared__ float sWT[HDIM * 96];
    __shared__ float sb[96];
    for (int i = threadIdx.x; i < 96 * HDIM; i += 256) {
        int j = i / HDIM, k = i % HDIM;
        sWT[k * 96 + j] = pWih[i];
    }
    for (int i = threadIdx.x; i < 96; i += 256)
        sb[i] = pbih[i] + (i < 64 ? pbhh[i] : 0.f);
    __syncthreads();
    int w = ((blockIdx.x - HB) * 256 + threadIdx.x) >> 5;
    int lane = threadIdx.x & 31;
    if (w < NLINKS) gi_warp(w, lane, sWT, sb);
}

// ---------------- scan (offsets + cursors) ---------------------------------
__global__ void k_scan() {
    __shared__ int part[1024];
    int tid = threadIdx.x;
    const int CH = (NLINKS + 1023) / 1024;
    int base = tid * CH;
    int s = 0;
    for (int i = 0; i < CH; i++) {
        int idx = base + i;
        if (idx < NLINKS) s += g_hist[idx];
    }
    part[tid] = s;
    __syncthreads();
    for (int off = 1; off < 1024; off <<= 1) {
        int add = (tid >= off) ? part[tid - off] : 0;
        __syncthreads();
        part[tid] += add;
        __syncthreads();
    }
    int run = (tid == 0) ? 0 : part[tid - 1];
    for (int i = 0; i < CH; i++) {
        int idx = base + i;
        if (idx < NLINKS) {
            g_off[idx] = run;
            g_cur[idx] = run;
            run += g_hist[idx];
        }
    }
    if (tid == 1023) g_off[NLINKS] = part[1023];
}

// ---------------- path GRU (dominant kernel) ----------------
// ONE warp per CTA, 2 paths per thread (64 paths/CTA). Weight LDS.128
// broadcasts amortized over both paths. hA/hB registers hold the OLD hidden
// through the whole j4 loop; blended pairs go to sH only (register-budget:
// 12 ULL accumulators, pairwise blend with immediate 8B store).
__global__ __launch_bounds__(32) void k_path(
    int build, const float* __restrict__ pWhh, const float* __restrict__ pbhh) {
    __shared__ __align__(16) float sW[96 * HDIM];   // 12.3 KB
    __shared__ __align__(16) float sBn[HDIM];
    __shared__ __align__(16) float sGi[64 * 100];   // 25.6 KB
    __shared__ __align__(16) float sH[64 * 36];     // 9.2 KB
    __shared__ int sLk[64];

    int lane = threadIdx.x;
    {
        const float4* src = (const float4*)pWhh;
        float4* dst = (float4*)sW;
#pragma unroll
        for (int i = 0; i < 24; i++) dst[i * 32 + lane] = src[i * 32 + lane];
        sBn[lane] = pbhh[64 + lane];
    }
    __syncwarp();

    int pbase = blockIdx.x * 64;
    int p0 = pbase + lane;
    int p1 = p0 + 32;
    bool v1 = (p1 < NPATHS);
    int p1s = v1 ? p1 : p0;
    unsigned sgi_base = (unsigned)__cvta_generic_to_shared(sGi);

    ULL hA[16], hB[16];
    {
        const ulonglong2* sA = (const ulonglong2*)&g_path_state[p0 * HDIM];
        const ulonglong2* sB = (const ulonglong2*)&g_path_state[p1s * HDIM];
#pragma unroll
        for (int i = 0; i < 8; i++) {
            ulonglong2 a = sA[i], b = sB[i];
            hA[2 * i] = a.x; hA[2 * i + 1] = a.y;
            hB[2 * i] = b.x; hB[2 * i + 1] = b.y;
        }
    }

    int lk0 = g_lk[p0 * PLEN];
    int lk1 = g_lk[p1s * PLEN];

    const float* gi0 = &sGi[lane * 100];
    const float* gi1 = &sGi[(lane + 32) * 100];
    float* myH0 = &sH[lane * 36];
    float* myH1 = &sH[(lane + 32) * 36];

#pragma unroll 1
    for (int s = 0; s < PLEN; s++) {
        sLk[lane] = lk0;
        sLk[32 + lane] = lk1;
        __syncwarp();
        // stage 64 gi rows (64 x 384B) coalesced: 48 x 16B per lane
#pragma unroll
        for (int it = 0; it < 48; it++) {
            int idx = it * 32 + lane;
            int m = idx / 24;
            int c = idx - m * 24;
            int row = sLk[m];
            const float* srcp = &g_gi[row * 96 + c * 4];
            unsigned dst = sgi_base + (unsigned)(m * 400 + c * 16);
            asm volatile("cp.async.cg.shared.global [%0], [%1], 16;" :: "r"(dst), "l"(srcp));
        }
        asm volatile("cp.async.commit_group;");

        if (build) {
            int pos0 = atomicAdd(&g_cur[lk0], 1);
            g_srow[pos0] = s * NPATHS + p0;
            if (v1) {
                int pos1 = atomicAdd(&g_cur[lk1], 1);
                g_srow[pos1] = s * NPATHS + p1;
            }
        }
        // prefetch next step's links
        if (s + 1 < PLEN) {
            lk0 = g_lk[p0 * PLEN + s + 1];
            lk1 = g_lk[p1s * PLEN + s + 1];
        }
        asm volatile("cp.async.wait_group 0;" ::: "memory");
        __syncwarp();

#pragma unroll 1
        for (int j4 = 0; j4 < 8; j4++) {
            float4 gr0 = *(const float4*)(gi0 + j4 * 4);
            float4 gz0 = *(const float4*)(gi0 + 32 + j4 * 4);
            float4 gn0 = *(const float4*)(gi0 + 64 + j4 * 4);
            float4 gr1 = *(const float4*)(gi1 + j4 * 4);
            float4 gz1 = *(const float4*)(gi1 + 32 + j4 * 4);
            float4 gn1 = *(const float4*)(gi1 + 64 + j4 * 4);
            float4 bn4 = *(const float4*)(sBn + j4 * 4);

#pragma unroll
            for (int half = 0; half < 2; half++) {
                float zA2[2], nA2[2], zB2[2], nB2[2];
#pragma unroll
                for (int v = 0; v < 2; v++) {
                    int u = half * 2 + v;
                    int jj = j4 * 4 + u;
                    // single accumulator chain per gate per path (12 ULL live)
                    ULL arA = 0, azA = 0, anA = 0;
                    ULL arB = 0, azB = 0, anB = 0;
                    const ulonglong2* wr = (const ulonglong2*)&sW[jj * HDIM];
                    const ulonglong2* wz = (const ulonglong2*)&sW[(32 + jj) * HDIM];
                    const ulonglong2* wn = (const ulonglong2*)&sW[(64 + jj) * HDIM];
#pragma unroll
                    for (int q = 0; q < 8; q++) {
                        ulonglong2 w;
                        w = wr[q];
                        arA = fma2(hA[2 * q], w.x, arA); arA = fma2(hA[2 * q + 1], w.y, arA);
                        arB = fma2(hB[2 * q], w.x, arB); arB = fma2(hB[2 * q + 1], w.y, arB);
                        w = wz[q];
                        azA = fma2(hA[2 * q], w.x, azA); azA = fma2(hA[2 * q + 1], w.y, azA);
                        azB = fma2(hB[2 * q], w.x, azB); azB = fma2(hB[2 * q + 1], w.y, azB);
                        w = wn[q];
                        anA = fma2(hA[2 * q], w.x, anA); anA = fma2(hA[2 * q + 1], w.y, anA);
                        anB = fma2(hB[2 * q], w.x, anB); anB = fma2(hB[2 * q + 1], w.y, anB);
                    }
                    float girA = (u == 0) ? gr0.x : (u == 1) ? gr0.y : (u == 2) ? gr0.z : gr0.w;
                    float gizA = (u == 0) ? gz0.x : (u == 1) ? gz0.y : (u == 2) ? gz0.z : gz0.w;
                    float ginA = (u == 0) ? gn0.x : (u == 1) ? gn0.y : (u == 2) ? gn0.z : gn0.w;
                    float girB = (u == 0) ? gr1.x : (u == 1) ? gr1.y : (u == 2) ? gr1.z : gr1.w;
                    float gizB = (u == 0) ? gz1.x : (u == 1) ? gz1.y : (u == 2) ? gz1.z : gz1.w;
                    float ginB = (u == 0) ? gn1.x : (u == 1) ? gn1.y : (u == 2) ? gn1.z : gn1.w;
                    float bnv = (u == 0) ? bn4.x : (u == 1) ? bn4.y : (u == 2) ? bn4.z : bn4.w;

                    float rA = sigmoid_fast(girA + hsum2(arA));
                    zA2[v] = sigmoid_fast(gizA + hsum2(azA));
                    nA2[v] = tanh_fast(ginA + rA * (hsum2(anA) + bnv));
                    float rB = sigmoid_fast(girB + hsum2(arB));
                    zB2[v] = sigmoid_fast(gizB + hsum2(azB));
                    nB2[v] = tanh_fast(ginB + rB * (hsum2(anB) + bnv));
                }
                // blend this pair against OLD h (registers untouched) -> sH only
                ULL aN = fma2(pk(zA2[0], zA2[1]), hA[2 * j4 + half],
                              mul2(pk(1.f - zA2[0], 1.f - zA2[1]), pk(nA2[0], nA2[1])));
                ULL bN = fma2(pk(zB2[0], zB2[1]), hB[2 * j4 + half],
                              mul2(pk(1.f - zB2[0], 1.f - zB2[1]), pk(nB2[0], nB2[1])));
                ((ULL*)myH0)[2 * j4 + half] = aN;
                ((ULL*)myH1)[2 * j4 + half] = bN;
            }
        }

        // refresh registers with the new hidden (after ALL gates computed)
#pragma unroll
        for (int i = 0; i < 8; i++) {
            ulonglong2 a = ((const ulonglong2*)myH0)[i];
            ulonglong2 b = ((const ulonglong2*)myH1)[i];
            hA[2 * i] = a.x; hA[2 * i + 1] = a.y;
            hB[2 * i] = b.x; hB[2 * i + 1] = b.y;
        }

        __syncwarp();
        // vectorized transpose store: 64 rows x 32 floats = 512 float4
#pragma unroll
        for (int i = 0; i < 16; i++) {
            int fidx = i * 32 + lane;
            int row = fidx >> 3;
            int c = (fidx & 7) * 4;
            float4 v = *(const float4*)&sH[row * 36 + c];
            int pp = pbase + row;
            if (pp < NPATHS)
                *(float4*)&g_hs[((size_t)s * NPATHS + pp) * HDIM + c] = v;
        }
        __syncwarp();
    }

    {
        ulonglong2* dA = (ulonglong2*)&g_path_state[p0 * HDIM];
#pragma unroll
        for (int i = 0; i < 8; i++) {
            ulonglong2 v; v.x = hA[2 * i]; v.y = hA[2 * i + 1];
            dA[i] = v;
        }
        if (v1) {
            ulonglong2* dB = (ulonglong2*)&g_path_state[p1 * HDIM];
#pragma unroll
            for (int i = 0; i < 8; i++) {
                ulonglong2 v; v.x = hB[2 * i]; v.y = hB[2 * i + 1];
                dB[i] = v;
            }
        }
    }
}

// ---------- link aggregation + link GRU + fused next-round gi --------------
__global__ __launch_bounds__(256) void k_link(
    int dogi,
    const float* __restrict__ lWih, const float* __restrict__ lWhh,
    const float* __restrict__ lbih, const float* __restrict__ lbhh,
    const float* __restrict__ pWih, const float* __restrict__ pbih,
    const float* __restrict__ pbhh) {
    __shared__ float sWihT[3 * HDIM * HDIM];  // [k][j]
    __shared__ float sWhhT[3 * HDIM * HDIM];
    __shared__ float sPT[3 * HDIM * HDIM];    // path Wih^T for gi
    __shared__ float sbi[96], sbh[96], sgb[96];

    for (int i = threadIdx.x; i < 3 * HDIM * HDIM; i += 256) {
        int j = i / HDIM, k = i % HDIM;
        sWihT[k * 96 + j] = lWih[i];
        sWhhT[k * 96 + j] = lWhh[i];
        sPT[k * 96 + j] = pWih[i];
    }
    for (int i = threadIdx.x; i < 96; i += 256) {
        sbi[i] = lbih[i];
        sbh[i] = lbhh[i];
        sgb[i] = pbih[i] + (i < 64 ? pbhh[i] : 0.f);
    }
    __syncthreads();

    int w = (blockIdx.x * 256 + threadIdx.x) >> 5;
    int lane = threadIdx.x & 31;
    if (w >= NLINKS) return;

    int b = g_off[w], e = g_off[w + 1];
    float x0 = 0.f, x1 = 0.f, x2s = 0.f, x3 = 0.f;
    int i = b;
    for (; i + 4 <= e; i += 4) {
        int r0 = g_srow[i], r1 = g_srow[i + 1], r2 = g_srow[i + 2], r3 = g_srow[i + 3];
        x0 += g_hs[(size_t)r0 * HDIM + lane];
        x1 += g_hs[(size_t)r1 * HDIM + lane];
        x2s += g_hs[(size_t)r2 * HDIM + lane];
        x3 += g_hs[(size_t)r3 * HDIM + lane];
    }
    for (; i < e; i++) x0 += g_hs[(size_t)g_srow[i] * HDIM + lane];
    float x = (x0 + x1) + (x2s + x3);

    float h = g_link_state[w * HDIM + lane];

    float air = sbi[lane], aiz = sbi[32 + lane], ain = sbi[64 + lane];
    float ahr = sbh[lane], ahz = sbh[32 + lane], ahn = sbh[64 + lane];
#pragma unroll
    for (int k = 0; k < 32; k++) {
        float xv = __shfl_sync(0xffffffffu, x, k);
        float hv = __shfl_sync(0xffffffffu, h, k);
        air += xv * sWihT[k * 96 + lane];
        aiz += xv * sWihT[k * 96 + 32 + lane];
        ain += xv * sWihT[k * 96 + 64 + lane];
        ahr += hv * sWhhT[k * 96 + lane];
        ahz += hv * sWhhT[k * 96 + 32 + lane];
        ahn += hv * sWhhT[k * 96 + 64 + lane];
    }
    float r = sigmoid_fast(air + ahr);
    float z = sigmoid_fast(aiz + ahz);
    float nv = tanh_fast(ain + r * ahn);
    float hnew = (1.f - z) * nv + z * h;
    g_link_state[w * HDIM + lane] = hnew;

    if (dogi) {
        float a0 = sgb[lane], a1 = sgb[32 + lane], a2 = sgb[64 + lane];
#pragma unroll
        for (int k = 0; k < 32; k++) {
            float hv = __shfl_sync(0xffffffffu, hnew, k);
            a0 += hv * sPT[k * 96 + lane];
            a1 += hv * sPT[k * 96 + 32 + lane];
            a2 += hv * sPT[k * 96 + 64 + lane];
        }
        g_gi[w * 96 + lane] = a0;
        g_gi[w * 96 + 32 + lane] = a1;
        g_gi[w * 96 + 64 + lane] = a2;
    }
}

// ---------------- readout MLP ----------------
__global__ __launch_bounds__(256) void k_readout(
    const float* __restrict__ W1, const float* __restrict__ b1,
    const float* __restrict__ W2, const float* __restrict__ b2,
    const float* __restrict__ W3, const float* __restrict__ b3,
    float* __restrict__ out) {
    __shared__ float s1[RDIM * HDIM], sb1[RDIM], s2[RDIM * RDIM], sb2[RDIM], s3[RDIM], sb3;
    for (int i = threadIdx.x; i < RDIM * HDIM; i += 256) s1[i] = W1[i];
    if (threadIdx.x < RDIM * RDIM) s2[threadIdx.x] = W2[threadIdx.x];
    if (threadIdx.x < RDIM) {
        sb1[threadIdx.x] = b1[threadIdx.x];
        sb2[threadIdx.x] = b2[threadIdx.x];
        s3[threadIdx.x] = W3[threadIdx.x];
    }
    if (threadIdx.x == 0) sb3 = b3[0];
    __syncthreads();

    int p = blockIdx.x * 256 + threadIdx.x;
    if (p >= NPATHS) return;

    float x[HDIM];
    {
        const float4* src = (const float4*)&g_path_state[p * HDIM];
#pragma unroll
        for (int i = 0; i < 8; i++) {
            float4 v = src[i];
            x[4 * i] = v.x; x[4 * i + 1] = v.y; x[4 * i + 2] = v.z; x[4 * i + 3] = v.w;
        }
    }
    float y1[RDIM];
#pragma unroll
    for (int i = 0; i < RDIM; i++) {
        float d = sb1[i];
#pragma unroll
        for (int k = 0; k < HDIM; k++) d += x[k] * s1[i * HDIM + k];
        y1[i] = fmaxf(d, 0.f);
    }
    float y2[RDIM];
#pragma unroll
    for (int i = 0; i < RDIM; i++) {
        float d = sb2[i];
#pragma unroll
        for (int k = 0; k < RDIM; k++) d += y1[k] * s2[i * RDIM + k];
        y2[i] = fmaxf(d, 0.f);
    }
    float o = sb3;
#pragma unroll
    for (int k = 0; k < RDIM; k++) o += y2[k] * s3[k];
    out[p] = o;
}

// ---------------- launch ----------------
extern "C" void kernel_launch(void* const* d_in, const int* in_sizes, int n_in,
                              void* d_out, int out_size) {
    const int* links = (const int*)d_in[0];
    const int* paths = (const int*)d_in[1];
    const int* seqs  = (const int*)d_in[2];
    const float* cap = (const float*)d_in[3];
    const float* bw  = (const float*)d_in[4];
    const float* pWih = (const float*)d_in[5];
    const float* pWhh = (const float*)d_in[6];
    const float* pbih = (const float*)d_in[7];
    const float* pbhh = (const float*)d_in[8];
    const float* lWih = (const float*)d_in[9];
    const float* lWhh = (const float*)d_in[10];
    const float* lbih = (const float*)d_in[11];
    const float* lbhh = (const float*)d_in[12];
    const float* W1 = (const float*)d_in[13];
    const float* b1 = (const float*)d_in[14];
    const float* W2 = (const float*)d_in[15];
    const float* b2 = (const float*)d_in[16];
    const float* W3 = (const float*)d_in[17];
    const float* b3 = (const float*)d_in[18];
    float* out = (float*)d_out;

    (void)in_sizes; (void)n_in; (void)out_size;

    k_setupA<<<(NPATHS * HDIM + 255) / 256, 256>>>(cap, bw, paths, seqs, links);
    k_setupB<<<HB + GB, 256>>>(links, pWih, pbih, pbhh);
    k_scan<<<1, 1024>>>();

    for (int r = 0; r < TROUNDS; r++) {
        k_path<<<(NPATHS + 63) / 64, 32>>>(r == 0 ? 1 : 0, pWhh, pbhh);
        k_link<<<(NLINKS + 7) / 8, 256>>>(r + 1 < TROUNDS ? 1 : 0,
                                          lWih, lWhh, lbih, lbhh,
                                          pWih, pbih, pbhh);
    }
    k_readout<<<(NPATHS + 255) / 256, 256>>>(W1, b1, W2, b2, W3, b3, out);
}